// round 7
// baseline (speedup 1.0000x reference)
#include <cuda_runtime.h>
#include <cuda_bf16.h>
#include <cstdint>

// ---------------- problem constants ----------------
#define BB 8
#define DD 64
#define TT 8192
#define KK 1024
#define NROWS 65536
#define NZ 4194304
#define THREADS 128
#define NBLOCKS 512
#define NC 64                 // codes per chunk
#define NCHUNKS 16

// ---------------- device scratch (no allocs allowed) ----------------
__device__ float g_wnorm[KK];
__device__ float g_partial[NBLOCKS];
__device__ unsigned int g_ticket;     // zero-init; reset by last block every run
__device__ __align__(16) __nv_bfloat16 g_wh[KK * DD];   // fragment-permuted rows
__device__ __align__(16) __nv_bfloat16 g_wl[KK * DD];

// ---------------- SMEM layout (dynamic, 56320 B -> 4 CTAs/SM) ----------------
#define B_ROW_STRIDE 144              // 128B data + 16B pad -> conflict-free LDS.128
#define B_PART (64 * B_ROW_STRIDE)    // 9216 B per (chunk, hi/lo part)
#define B_BUF  (2 * B_PART)           // 18432 B per buffer (hi+lo)
#define SM_B    0                     // 3 buffers: 55296 B (also reused for z staging)
#define SM_ZN   55296                 // znorm[128]: 512 B
#define SM_RED  55808                 // loss reduction[128]: 512 B
#define SM_SIZE 56320

// ---------------- helpers ----------------
__device__ __forceinline__ uint32_t smem_u32(const void* p) {
    uint32_t a;
    asm("{ .reg .u64 t; cvta.to.shared.u64 t, %1; cvt.u32.u64 %0, t; }" : "=r"(a) : "l"(p));
    return a;
}
__device__ __forceinline__ void cp_async16(uint32_t dst, const void* src) {
    asm volatile("cp.async.cg.shared.global [%0], [%1], 16;" :: "r"(dst), "l"(src));
}
#define CP_COMMIT()  asm volatile("cp.async.commit_group;" ::: "memory")
#define CP_WAIT(n)   asm volatile("cp.async.wait_group %0;" :: "n"(n) : "memory")

// packed f32x2 (sm_103 packed fp32 pipe)
__device__ __forceinline__ unsigned long long pk2(float lo, float hi) {
    unsigned long long r;
    asm("mov.b64 %0, {%1, %2};" : "=l"(r) : "f"(lo), "f"(hi));
    return r;
}
__device__ __forceinline__ void unpk2(unsigned long long v, float& lo, float& hi) {
    asm("mov.b64 {%0, %1}, %2;" : "=f"(lo), "=f"(hi) : "l"(v));
}
__device__ __forceinline__ unsigned long long fma2(unsigned long long a, unsigned long long b, unsigned long long c) {
    unsigned long long d;
    asm("fma.rn.f32x2 %0, %1, %2, %3;" : "=l"(d) : "l"(a), "l"(b), "l"(c));
    return d;
}
__device__ __forceinline__ unsigned long long add2(unsigned long long a, unsigned long long b) {
    unsigned long long d;
    asm("add.rn.f32x2 %0, %1, %2;" : "=l"(d) : "l"(a), "l"(b));
    return d;
}

// m16n8k16 bf16 MMA, fp32 accumulate
#define MMA_BF16(acc, a, b) \
    asm volatile("mma.sync.aligned.m16n8k16.row.col.f32.bf16.bf16.f32 " \
        "{%0,%1,%2,%3},{%4,%5,%6,%7},{%8,%9},{%0,%1,%2,%3};" \
        : "+f"((acc)[0]), "+f"((acc)[1]), "+f"((acc)[2]), "+f"((acc)[3]) \
        : "r"((a)[0]), "r"((a)[1]), "r"((a)[2]), "r"((a)[3]), \
          "r"((b)[0]), "r"((b)[1]))

__device__ __forceinline__ void split2(float a, float b, uint32_t& h, uint32_t& lo) {
    __nv_bfloat16 ha = __float2bfloat16(a), hb = __float2bfloat16(b);
    float ra = __fsub_rn(a, __bfloat162float(ha));
    float rb = __fsub_rn(b, __bfloat162float(hb));
    __nv_bfloat16 la = __float2bfloat16(ra), lb = __float2bfloat16(rb);
    h  = (uint32_t)__bfloat16_as_ushort(ha) | ((uint32_t)__bfloat16_as_ushort(hb) << 16);
    lo = (uint32_t)__bfloat16_as_ushort(la) | ((uint32_t)__bfloat16_as_ushort(lb) << 16);
}

// fragment permutation: element kk (0..63) of a W row -> bf16 slot
// kk = kt*16 + half*8 + 2*t + e  ->  idx = t*16 + kt*4 + half*2 + e
__device__ __host__ __forceinline__ int permidx(int kk) {
    int kt = kk >> 4, r = kk & 15;
    int half = r >> 3, s = r & 7, tq = s >> 1, e = s & 1;
    return tq * 16 + kt * 4 + half * 2 + e;
}

// ---------------- prep: wnorm (R1-identical rounding order) + permuted bf16 split ----------------
__global__ void vq_prep_kernel(const float* __restrict__ W) {
    int k = blockIdx.x * blockDim.x + threadIdx.x;
    if (k >= KK) return;
    const float4* wr = reinterpret_cast<const float4*>(W + (size_t)k * DD);
    float t32[32];
    uint32_t uh[32], ul[32];
#pragma unroll
    for (int i = 0; i < 32; i++) { uh[i] = 0; ul[i] = 0; }
#pragma unroll
    for (int j = 0; j < 8; j++) {
        float4 va = wr[j];
        float4 vb = wr[j + 8];
        float av[4] = {va.x, va.y, va.z, va.w};
        float bv[4] = {vb.x, vb.y, vb.z, vb.w};
#pragma unroll
        for (int q = 0; q < 4; q++) {
            t32[4 * j + q] = __fadd_rn(__fmul_rn(av[q], av[q]), __fmul_rn(bv[q], bv[q]));
            {
                int idx = permidx(4 * j + q);
                __nv_bfloat16 h = __float2bfloat16(av[q]);
                __nv_bfloat16 l = __float2bfloat16(__fsub_rn(av[q], __bfloat162float(h)));
                uh[idx >> 1] |= (uint32_t)__bfloat16_as_ushort(h) << (16 * (idx & 1));
                ul[idx >> 1] |= (uint32_t)__bfloat16_as_ushort(l) << (16 * (idx & 1));
            }
            {
                int idx = permidx(4 * j + q + 32);
                __nv_bfloat16 h = __float2bfloat16(bv[q]);
                __nv_bfloat16 l = __float2bfloat16(__fsub_rn(bv[q], __bfloat162float(h)));
                uh[idx >> 1] |= (uint32_t)__bfloat16_as_ushort(h) << (16 * (idx & 1));
                ul[idx >> 1] |= (uint32_t)__bfloat16_as_ushort(l) << (16 * (idx & 1));
            }
        }
    }
#pragma unroll
    for (int off = 16; off >= 1; off >>= 1) {
#pragma unroll
        for (int j = 0; j < 16; j++) {
            if (j < off) t32[j] = __fadd_rn(t32[j], t32[j + off]);
        }
    }
    g_wnorm[k] = t32[0];
    uint4* dh = reinterpret_cast<uint4*>(g_wh + (size_t)k * DD);
    uint4* dl = reinterpret_cast<uint4*>(g_wl + (size_t)k * DD);
#pragma unroll
    for (int i = 0; i < 8; i++) {
        dh[i] = make_uint4(uh[4 * i], uh[4 * i + 1], uh[4 * i + 2], uh[4 * i + 3]);
        dl[i] = make_uint4(ul[4 * i], ul[4 * i + 1], ul[4 * i + 2], ul[4 * i + 3]);
    }
}

// ---------------- chunk prefetch via cp.async ----------------
__device__ __forceinline__ void issue_chunk(uint32_t sb, int chunk, int buf, int tid) {
    const uint4* srcH = reinterpret_cast<const uint4*>(g_wh + (size_t)chunk * NC * DD);
    const uint4* srcL = reinterpret_cast<const uint4*>(g_wl + (size_t)chunk * NC * DD);
    uint32_t dH = sb + SM_B + buf * B_BUF;
    uint32_t dL = dH + B_PART;
#pragma unroll
    for (int i = 0; i < 4; i++) {
        int idx = tid + i * THREADS;          // 0..511 -> row=idx/8, 16B col=idx%8
        uint32_t off = (uint32_t)(idx >> 3) * B_ROW_STRIDE + (uint32_t)(idx & 7) * 16;
        cp_async16(dH + off, srcH + idx);
        cp_async16(dL + off, srcL + idx);
    }
}

// ---------------- per-chunk: 24 HMMA (6 indep chains) x 8nt + packed dist + argmin ----------------
__device__ __forceinline__ void process_chunk(
    const char* smp, int c, int g, int t,
    const uint32_t ah[2][4][4], const uint32_t al[2][4][4],
    const unsigned long long zpkA[2], const unsigned long long zpkB[2],
    unsigned long long NEG2, float dmin[4], int imin[4])
{
    const char* bbase = smp + SM_B + (c % 3) * B_BUF;
#pragma unroll
    for (int nt = 0; nt < 8; nt++) {
        const char* rowp = bbase + (nt * 8 + g) * B_ROW_STRIDE + t * 32;
        uint4 h0 = *reinterpret_cast<const uint4*>(rowp);
        uint4 h1 = *reinterpret_cast<const uint4*>(rowp + 16);
        uint4 l0 = *reinterpret_cast<const uint4*>(rowp + B_PART);
        uint4 l1 = *reinterpret_cast<const uint4*>(rowp + B_PART + 16);
        uint32_t bh[4][2] = {{h0.x, h0.y}, {h0.z, h0.w}, {h1.x, h1.y}, {h1.z, h1.w}};
        uint32_t bl[4][2] = {{l0.x, l0.y}, {l0.z, l0.w}, {l1.x, l1.y}, {l1.z, l1.w}};

        // 6 independent accumulator chains (hh/hl/lh x mt) -> chain length 4
        float ahh[2][4] = {{0.f,0.f,0.f,0.f},{0.f,0.f,0.f,0.f}};
        float ahl[2][4] = {{0.f,0.f,0.f,0.f},{0.f,0.f,0.f,0.f}};
        float alh[2][4] = {{0.f,0.f,0.f,0.f},{0.f,0.f,0.f,0.f}};
#pragma unroll
        for (int kt = 0; kt < 4; kt++) {
#pragma unroll
            for (int mt = 0; mt < 2; mt++) {
                MMA_BF16(ahh[mt], ah[mt][kt], bh[kt]);
                MMA_BF16(ahl[mt], ah[mt][kt], bl[kt]);
                MMA_BF16(alh[mt], al[mt][kt], bh[kt]);
            }
        }

        const int cb = c * 64 + nt * 8 + 2 * t;
        const float2 wnv = __ldg(reinterpret_cast<const float2*>(g_wnorm + cb));
        const unsigned long long wpk = pk2(wnv.x, wnv.y);
#pragma unroll
        for (int mt = 0; mt < 2; mt++) {
            float s0 = (ahh[mt][0] + ahl[mt][0]) + alh[mt][0];
            float s1 = (ahh[mt][1] + ahl[mt][1]) + alh[mt][1];
            float s2 = (ahh[mt][2] + ahl[mt][2]) + alh[mt][2];
            float s3 = (ahh[mt][3] + ahl[mt][3]) + alh[mt][3];
            // per lane: fadd(fma(s, -2, znorm), wn) == fadd(fsub(znorm, 2s), wn) bitwise (2s exact)
            unsigned long long dA = add2(fma2(pk2(s0, s1), NEG2, zpkA[mt]), wpk);
            unsigned long long dB = add2(fma2(pk2(s2, s3), NEG2, zpkB[mt]), wpk);
            float d0, d1, d2, d3;
            unpk2(dA, d0, d1);
            unpk2(dB, d2, d3);
            if (d0 < dmin[2 * mt])     { dmin[2 * mt] = d0;     imin[2 * mt] = cb; }
            if (d1 < dmin[2 * mt])     { dmin[2 * mt] = d1;     imin[2 * mt] = cb + 1; }
            if (d2 < dmin[2 * mt + 1]) { dmin[2 * mt + 1] = d2; imin[2 * mt + 1] = cb; }
            if (d3 < dmin[2 * mt + 1]) { dmin[2 * mt + 1] = d3; imin[2 * mt + 1] = cb + 1; }
        }
    }
}

// ---------------- main kernel (finalize fused via last-block ticket) ----------------
__global__ __launch_bounds__(THREADS, 4)
void vq_main_kernel(const float* __restrict__ z,
                    const float* __restrict__ W,
                    float* __restrict__ out_zq,
                    float* __restrict__ out_codes,
                    float* __restrict__ out_loss) {
    extern __shared__ __align__(16) char smp[];
    const uint32_t sb = smem_u32(smp);

    const int tid = threadIdx.x;
    const int w = tid >> 5;
    const int l = tid & 31;
    const int g = l >> 2;
    const int t = l & 3;

    // ---- stage z rows into smem (reuses B region) + znorm (R1-identical tree) ----
    {
        const int grow = blockIdx.x * THREADS + tid;
        const float* zp = z + (size_t)(grow >> 13) * DD * TT + (grow & (TT - 1));
        float* zr = reinterpret_cast<float*>(smp) + tid * 65;
        float sq[32];
#pragma unroll
        for (int j = 0; j < 32; j++) {
            float v0 = zp[(size_t)(2 * j) * TT];
            float v1 = zp[(size_t)(2 * j + 1) * TT];
            zr[2 * j] = v0;
            zr[2 * j + 1] = v1;
            sq[j] = __fadd_rn(__fmul_rn(v0, v0), __fmul_rn(v1, v1));
        }
#pragma unroll
        for (int off = 16; off >= 1; off >>= 1) {
#pragma unroll
            for (int j = 0; j < 16; j++) {
                if (j < off) sq[j] = __fadd_rn(sq[j], sq[j + off]);
            }
        }
        reinterpret_cast<float*>(smp + SM_ZN)[tid] = sq[0];
    }
    __syncthreads();

    // ---- register-resident A fragments (zh, zl) ----
    uint32_t ah[2][4][4], al[2][4][4];
#pragma unroll
    for (int mt = 0; mt < 2; mt++) {
        const float* r0 = reinterpret_cast<const float*>(smp) + (w * 32 + mt * 16 + g) * 65;
        const float* r1 = r0 + 8 * 65;
#pragma unroll
        for (int kt = 0; kt < 4; kt++) {
            const int c0 = kt * 16 + 2 * t;
            split2(r0[c0],     r0[c0 + 1], ah[mt][kt][0], al[mt][kt][0]);
            split2(r1[c0],     r1[c0 + 1], ah[mt][kt][1], al[mt][kt][1]);
            split2(r0[c0 + 8], r0[c0 + 9], ah[mt][kt][2], al[mt][kt][2]);
            split2(r1[c0 + 8], r1[c0 + 9], ah[mt][kt][3], al[mt][kt][3]);
        }
    }
    unsigned long long zpkA[2], zpkB[2];
#pragma unroll
    for (int mt = 0; mt < 2; mt++) {
        float a = reinterpret_cast<const float*>(smp + SM_ZN)[w * 32 + g + 8 * (2 * mt)];
        float b = reinterpret_cast<const float*>(smp + SM_ZN)[w * 32 + g + 8 * (2 * mt + 1)];
        zpkA[mt] = pk2(a, a);
        zpkB[mt] = pk2(b, b);
    }
    const unsigned long long NEG2 = pk2(-2.0f, -2.0f);
    __syncthreads();   // z staging region now free -> becomes B buffers

    // ---- prefetch chunks 0,1 ----
    issue_chunk(sb, 0, 0, tid); CP_COMMIT();
    issue_chunk(sb, 1, 1, tid); CP_COMMIT();

    float dmin[4] = {3.4e38f, 3.4e38f, 3.4e38f, 3.4e38f};
    int imin[4] = {0, 0, 0, 0};

    // ---- pipeline: ONE barrier per chunk, cp.async 2 ahead, 3 buffers ----
    for (int c = 0; c < NCHUNKS - 1; c++) {
        CP_WAIT(1);            // chunk c resident (chunk c+1 may still be in flight)
        __syncthreads();       // also guarantees all warps done with chunk c-1 (buf (c+2)%3)
        if (c + 2 < NCHUNKS) { issue_chunk(sb, c + 2, (c + 2) % 3, tid); CP_COMMIT(); }
        process_chunk(smp, c, g, t, ah, al, zpkA, zpkB, NEG2, dmin, imin);
    }
    CP_WAIT(0);
    __syncthreads();
    process_chunk(smp, NCHUNKS - 1, g, t, ah, al, zpkA, zpkB, NEG2, dmin, imin);

    // ---- cross-lane reduce over the t-quad (smaller index wins ties) ----
#pragma unroll
    for (int s = 0; s < 4; s++) {
#pragma unroll
        for (int o = 1; o < 4; o <<= 1) {
            float od = __shfl_xor_sync(0xffffffff, dmin[s], o);
            int   oi = __shfl_xor_sync(0xffffffff, imin[s], o);
            if (od < dmin[s] || (od == dmin[s] && oi < imin[s])) { dmin[s] = od; imin[s] = oi; }
        }
    }
    const int my = (t == 0) ? imin[0] : (t == 1) ? imin[1] : (t == 2) ? imin[2] : imin[3];

    // ---- outputs: codes, z_q_st = z + (w - z), loss partial ----
    const int rown = w * 32 + g + 8 * t;
    const int grow = blockIdx.x * THREADS + rown;
    out_codes[grow] = (float)my;

    const int b = grow >> 13;
    const int tp = grow & (TT - 1);
    const float* zp = z + (size_t)b * DD * TT + tp;
    float* oz = out_zq + (size_t)b * DD * TT + tp;
    const float4* wrow = reinterpret_cast<const float4*>(W + (size_t)my * DD);
    float lsum = 0.0f;
#pragma unroll
    for (int j = 0; j < 16; j++) {
        float4 wv = wrow[j];
        float wa[4] = {wv.x, wv.y, wv.z, wv.w};
#pragma unroll
        for (int q = 0; q < 4; q++) {
            float zv = zp[(size_t)(4 * j + q) * TT];
            float e = __fsub_rn(wa[q], zv);
            oz[(size_t)(4 * j + q) * TT] = __fadd_rn(zv, e);   // straight-through estimator
            lsum = __fadd_rn(lsum, __fmul_rn(e, e));
        }
    }

    float* sRed = reinterpret_cast<float*>(smp + SM_RED);
    sRed[tid] = lsum;
    __syncthreads();
#pragma unroll
    for (int s = THREADS / 2; s > 0; s >>= 1) {
        if (tid < s) sRed[tid] += sRed[tid + s];
        __syncthreads();
    }

    // ---- fused finalize: last block reduces all partials (deterministic order) ----
    __shared__ unsigned int sIsLast;
    if (tid == 0) {
        g_partial[blockIdx.x] = sRed[0];
        __threadfence();
        unsigned int tk = atomicAdd(&g_ticket, 1u);
        sIsLast = (tk == NBLOCKS - 1) ? 1u : 0u;
    }
    __syncthreads();
    if (sIsLast) {
        float v = __fadd_rn(__fadd_rn(g_partial[tid], g_partial[tid + 128]),
                            __fadd_rn(g_partial[tid + 256], g_partial[tid + 384]));
        sRed[tid] = v;
        __syncthreads();
#pragma unroll
        for (int s = THREADS / 2; s > 0; s >>= 1) {
            if (tid < s) sRed[tid] += sRed[tid + s];
            __syncthreads();
        }
        if (tid == 0) {
            out_loss[0] = 1.25f * (sRed[0] / (float)NZ);
            g_ticket = 0;    // reset for next graph replay
        }
    }
}

extern "C" void kernel_launch(void* const* d_in, const int* in_sizes, int n_in,
                              void* d_out, int out_size) {
    const float* z = (const float*)d_in[0];      // [8, 64, 8192]
    const float* W = (const float*)d_in[1];      // [1024, 64]
    float* out = (float*)d_out;
    float* out_zq    = out;
    float* out_loss  = out + NZ;
    float* out_codes = out + NZ + 1;

    static bool attr_set = false;
    if (!attr_set) {
        cudaFuncSetAttribute(vq_main_kernel, cudaFuncAttributeMaxDynamicSharedMemorySize, SM_SIZE);
        attr_set = true;
    }

    vq_prep_kernel<<<32, 32>>>(W);
    vq_main_kernel<<<NBLOCKS, THREADS, SM_SIZE>>>(z, W, out_zq, out_codes, out_loss);
}

// round 8
// speedup vs baseline: 1.1025x; 1.1025x over previous
#include <cuda_runtime.h>
#include <cuda_bf16.h>
#include <cstdint>

// ---------------- problem constants ----------------
#define BB 8
#define DD 64
#define TT 8192
#define KK 1024
#define NROWS 65536
#define NZ 4194304
#define THREADS 128
#define NBLOCKS 512
#define NC 64                 // codes per chunk
#define NCHUNKS 16

// ---------------- device scratch (no allocs allowed) ----------------
__device__ float g_wnorm[KK];
__device__ float g_partial[NBLOCKS];
__device__ unsigned int g_ticket;     // zero-init; reset by last block every run
__device__ __align__(16) __nv_bfloat16 g_wh[KK * DD];   // fragment-permuted rows
__device__ __align__(16) __nv_bfloat16 g_wl[KK * DD];

// ---------------- static SMEM layout (41984 B -> 4 CTAs/SM) ----------------
#define B_ROW_STRIDE 144              // 128B data + 16B pad -> conflict-free LDS.128
#define B_PART (64 * B_ROW_STRIDE)    // 9216 B per (chunk, hi/lo part)
#define B_BUF  (2 * B_PART)           // 18432 B per buffer (hi+lo)
#define SM_B    0                     // 2 buffers: 36864 B (also reused for z staging)
#define SM_WN   36864                 // wnorm[1024] fp32: 4096 B
#define SM_ZN   40960                 // znorm[128]: 512 B
#define SM_RED  41472                 // loss reduction[128]: 512 B
#define SM_SIZE 41984

// ---------------- helpers ----------------
__device__ __forceinline__ uint32_t smem_u32(const void* p) {
    uint32_t a;
    asm("{ .reg .u64 t; cvta.to.shared.u64 t, %1; cvt.u32.u64 %0, t; }" : "=r"(a) : "l"(p));
    return a;
}
__device__ __forceinline__ void cp_async16(uint32_t dst, const void* src) {
    asm volatile("cp.async.cg.shared.global [%0], [%1], 16;" :: "r"(dst), "l"(src));
}
#define CP_COMMIT()  asm volatile("cp.async.commit_group;" ::: "memory")
#define CP_WAIT(n)   asm volatile("cp.async.wait_group %0;" :: "n"(n) : "memory")

// packed f32x2 (sm_103 packed fp32 pipe)
__device__ __forceinline__ unsigned long long pk2(float lo, float hi) {
    unsigned long long r;
    asm("mov.b64 %0, {%1, %2};" : "=l"(r) : "f"(lo), "f"(hi));
    return r;
}
__device__ __forceinline__ void unpk2(unsigned long long v, float& lo, float& hi) {
    asm("mov.b64 {%0, %1}, %2;" : "=f"(lo), "=f"(hi) : "l"(v));
}
__device__ __forceinline__ unsigned long long fma2(unsigned long long a, unsigned long long b, unsigned long long c) {
    unsigned long long d;
    asm("fma.rn.f32x2 %0, %1, %2, %3;" : "=l"(d) : "l"(a), "l"(b), "l"(c));
    return d;
}
__device__ __forceinline__ unsigned long long add2(unsigned long long a, unsigned long long b) {
    unsigned long long d;
    asm("add.rn.f32x2 %0, %1, %2;" : "=l"(d) : "l"(a), "l"(b));
    return d;
}

// m16n8k16 bf16 MMA, fp32 accumulate
#define MMA_BF16(acc, a, b) \
    asm volatile("mma.sync.aligned.m16n8k16.row.col.f32.bf16.bf16.f32 " \
        "{%0,%1,%2,%3},{%4,%5,%6,%7},{%8,%9},{%0,%1,%2,%3};" \
        : "+f"((acc)[0]), "+f"((acc)[1]), "+f"((acc)[2]), "+f"((acc)[3]) \
        : "r"((a)[0]), "r"((a)[1]), "r"((a)[2]), "r"((a)[3]), \
          "r"((b)[0]), "r"((b)[1]))

__device__ __forceinline__ void split2(float a, float b, uint32_t& h, uint32_t& lo) {
    __nv_bfloat16 ha = __float2bfloat16(a), hb = __float2bfloat16(b);
    float ra = __fsub_rn(a, __bfloat162float(ha));
    float rb = __fsub_rn(b, __bfloat162float(hb));
    __nv_bfloat16 la = __float2bfloat16(ra), lb = __float2bfloat16(rb);
    h  = (uint32_t)__bfloat16_as_ushort(ha) | ((uint32_t)__bfloat16_as_ushort(hb) << 16);
    lo = (uint32_t)__bfloat16_as_ushort(la) | ((uint32_t)__bfloat16_as_ushort(lb) << 16);
}

// fragment permutation: element kk (0..63) of a W row -> bf16 slot
// kk = kt*16 + half*8 + 2*t + e  ->  idx = t*16 + kt*4 + half*2 + e
__device__ __host__ __forceinline__ int permidx(int kk) {
    int kt = kk >> 4, r = kk & 15;
    int half = r >> 3, s = r & 7, tq = s >> 1, e = s & 1;
    return tq * 16 + kt * 4 + half * 2 + e;
}

// ---------------- prep: wnorm (R1-identical rounding order) + permuted bf16 split ----------------
__global__ void vq_prep_kernel(const float* __restrict__ W) {
    int k = blockIdx.x * blockDim.x + threadIdx.x;
    if (k >= KK) return;
    const float4* wr = reinterpret_cast<const float4*>(W + (size_t)k * DD);
    float t32[32];
    uint32_t uh[32], ul[32];
#pragma unroll
    for (int i = 0; i < 32; i++) { uh[i] = 0; ul[i] = 0; }
#pragma unroll
    for (int j = 0; j < 8; j++) {
        float4 va = wr[j];
        float4 vb = wr[j + 8];
        float av[4] = {va.x, va.y, va.z, va.w};
        float bv[4] = {vb.x, vb.y, vb.z, vb.w};
#pragma unroll
        for (int q = 0; q < 4; q++) {
            t32[4 * j + q] = __fadd_rn(__fmul_rn(av[q], av[q]), __fmul_rn(bv[q], bv[q]));
            {
                int idx = permidx(4 * j + q);
                __nv_bfloat16 h = __float2bfloat16(av[q]);
                __nv_bfloat16 l = __float2bfloat16(__fsub_rn(av[q], __bfloat162float(h)));
                uh[idx >> 1] |= (uint32_t)__bfloat16_as_ushort(h) << (16 * (idx & 1));
                ul[idx >> 1] |= (uint32_t)__bfloat16_as_ushort(l) << (16 * (idx & 1));
            }
            {
                int idx = permidx(4 * j + q + 32);
                __nv_bfloat16 h = __float2bfloat16(bv[q]);
                __nv_bfloat16 l = __float2bfloat16(__fsub_rn(bv[q], __bfloat162float(h)));
                uh[idx >> 1] |= (uint32_t)__bfloat16_as_ushort(h) << (16 * (idx & 1));
                ul[idx >> 1] |= (uint32_t)__bfloat16_as_ushort(l) << (16 * (idx & 1));
            }
        }
    }
#pragma unroll
    for (int off = 16; off >= 1; off >>= 1) {
#pragma unroll
        for (int j = 0; j < 16; j++) {
            if (j < off) t32[j] = __fadd_rn(t32[j], t32[j + off]);
        }
    }
    g_wnorm[k] = t32[0];
    uint4* dh = reinterpret_cast<uint4*>(g_wh + (size_t)k * DD);
    uint4* dl = reinterpret_cast<uint4*>(g_wl + (size_t)k * DD);
#pragma unroll
    for (int i = 0; i < 8; i++) {
        dh[i] = make_uint4(uh[4 * i], uh[4 * i + 1], uh[4 * i + 2], uh[4 * i + 3]);
        dl[i] = make_uint4(ul[4 * i], ul[4 * i + 1], ul[4 * i + 2], ul[4 * i + 3]);
    }
}

// ---------------- chunk prefetch via cp.async ----------------
__device__ __forceinline__ void issue_chunk(uint32_t sb, int chunk, int buf, int tid) {
    const uint4* srcH = reinterpret_cast<const uint4*>(g_wh + (size_t)chunk * NC * DD);
    const uint4* srcL = reinterpret_cast<const uint4*>(g_wl + (size_t)chunk * NC * DD);
    uint32_t dH = sb + SM_B + buf * B_BUF;
    uint32_t dL = dH + B_PART;
#pragma unroll
    for (int i = 0; i < 4; i++) {
        int idx = tid + i * THREADS;          // 0..511 -> row=idx/8, 16B col=idx%8
        uint32_t off = (uint32_t)(idx >> 3) * B_ROW_STRIDE + (uint32_t)(idx & 7) * 16;
        cp_async16(dH + off, srcH + idx);
        cp_async16(dL + off, srcL + idx);
    }
}

// ---------------- per-chunk: 24 HMMA (2 chains) x 8nt + packed dist + argmin ----------------
__device__ __forceinline__ void process_chunk(
    const char* smp, int c, int g, int t,
    const uint32_t ah[2][4][4], const uint32_t al[2][4][4],
    const unsigned long long zpkA[2], const unsigned long long zpkB[2],
    unsigned long long NEG2, float dmin[4], int imin[4])
{
    const char* bbase = smp + SM_B + (c & 1) * B_BUF;
#pragma unroll
    for (int nt = 0; nt < 8; nt++) {
        const char* rowp = bbase + (nt * 8 + g) * B_ROW_STRIDE + t * 32;
        uint4 h0 = *reinterpret_cast<const uint4*>(rowp);
        uint4 h1 = *reinterpret_cast<const uint4*>(rowp + 16);
        uint4 l0 = *reinterpret_cast<const uint4*>(rowp + B_PART);
        uint4 l1 = *reinterpret_cast<const uint4*>(rowp + B_PART + 16);
        uint32_t bh[4][2] = {{h0.x, h0.y}, {h0.z, h0.w}, {h1.x, h1.y}, {h1.z, h1.w}};
        uint32_t bl[4][2] = {{l0.x, l0.y}, {l0.z, l0.w}, {l1.x, l1.y}, {l1.z, l1.w}};
        float acc[2][4] = {{0.f, 0.f, 0.f, 0.f}, {0.f, 0.f, 0.f, 0.f}};
#pragma unroll
        for (int mt = 0; mt < 2; mt++) {
#pragma unroll
            for (int kt = 0; kt < 4; kt++) MMA_BF16(acc[mt], ah[mt][kt], bh[kt]);  // hh
#pragma unroll
            for (int kt = 0; kt < 4; kt++) MMA_BF16(acc[mt], ah[mt][kt], bl[kt]);  // hl
#pragma unroll
            for (int kt = 0; kt < 4; kt++) MMA_BF16(acc[mt], al[mt][kt], bh[kt]);  // lh
        }
        const int cb = c * 64 + nt * 8 + 2 * t;
        unsigned long long wpk = *reinterpret_cast<const unsigned long long*>(smp + SM_WN + (size_t)cb * 4);
#pragma unroll
        for (int mt = 0; mt < 2; mt++) {
            // per lane: fadd(fma(s, -2, znorm), wn) == fadd(fsub(znorm, 2s), wn) bitwise (2s exact)
            unsigned long long dA = add2(fma2(pk2(acc[mt][0], acc[mt][1]), NEG2, zpkA[mt]), wpk);
            unsigned long long dB = add2(fma2(pk2(acc[mt][2], acc[mt][3]), NEG2, zpkB[mt]), wpk);
            float d0, d1, d2, d3;
            unpk2(dA, d0, d1);
            unpk2(dB, d2, d3);
            if (d0 < dmin[2 * mt])     { dmin[2 * mt] = d0;     imin[2 * mt] = cb; }
            if (d1 < dmin[2 * mt])     { dmin[2 * mt] = d1;     imin[2 * mt] = cb + 1; }
            if (d2 < dmin[2 * mt + 1]) { dmin[2 * mt + 1] = d2; imin[2 * mt + 1] = cb; }
            if (d3 < dmin[2 * mt + 1]) { dmin[2 * mt + 1] = d3; imin[2 * mt + 1] = cb + 1; }
        }
    }
}

// ---------------- main kernel (finalize fused via last-block ticket) ----------------
__global__ __launch_bounds__(THREADS, 4)
void vq_main_kernel(const float* __restrict__ z,
                    const float* __restrict__ W,
                    float* __restrict__ out_zq,
                    float* __restrict__ out_codes,
                    float* __restrict__ out_loss) {
    __shared__ __align__(16) char smp[SM_SIZE];
    const uint32_t sb = smem_u32(smp);

    const int tid = threadIdx.x;
    const int w = tid >> 5;
    const int l = tid & 31;
    const int g = l >> 2;
    const int t = l & 3;

    // ---- stage z rows into smem (reuses B region) + znorm (R1-identical tree) ----
    {
        const int grow = blockIdx.x * THREADS + tid;
        const float* zp = z + (size_t)(grow >> 13) * DD * TT + (grow & (TT - 1));
        float* zr = reinterpret_cast<float*>(smp) + tid * 65;
        float sq[32];
#pragma unroll
        for (int j = 0; j < 32; j++) {
            float v0 = zp[(size_t)(2 * j) * TT];
            float v1 = zp[(size_t)(2 * j + 1) * TT];
            zr[2 * j] = v0;
            zr[2 * j + 1] = v1;
            sq[j] = __fadd_rn(__fmul_rn(v0, v0), __fmul_rn(v1, v1));
        }
#pragma unroll
        for (int off = 16; off >= 1; off >>= 1) {
#pragma unroll
            for (int j = 0; j < 16; j++) {
                if (j < off) sq[j] = __fadd_rn(sq[j], sq[j + off]);
            }
        }
        reinterpret_cast<float*>(smp + SM_ZN)[tid] = sq[0];
    }
    __syncthreads();

    // ---- register-resident A fragments (zh, zl) ----
    uint32_t ah[2][4][4], al[2][4][4];
#pragma unroll
    for (int mt = 0; mt < 2; mt++) {
        const float* r0 = reinterpret_cast<const float*>(smp) + (w * 32 + mt * 16 + g) * 65;
        const float* r1 = r0 + 8 * 65;
#pragma unroll
        for (int kt = 0; kt < 4; kt++) {
            const int c0 = kt * 16 + 2 * t;
            split2(r0[c0],     r0[c0 + 1], ah[mt][kt][0], al[mt][kt][0]);
            split2(r1[c0],     r1[c0 + 1], ah[mt][kt][1], al[mt][kt][1]);
            split2(r0[c0 + 8], r0[c0 + 9], ah[mt][kt][2], al[mt][kt][2]);
            split2(r1[c0 + 8], r1[c0 + 9], ah[mt][kt][3], al[mt][kt][3]);
        }
    }
    unsigned long long zpkA[2], zpkB[2];
#pragma unroll
    for (int mt = 0; mt < 2; mt++) {
        float a = reinterpret_cast<const float*>(smp + SM_ZN)[w * 32 + g + 8 * (2 * mt)];
        float b = reinterpret_cast<const float*>(smp + SM_ZN)[w * 32 + g + 8 * (2 * mt + 1)];
        zpkA[mt] = pk2(a, a);
        zpkB[mt] = pk2(b, b);
    }
    const unsigned long long NEG2 = pk2(-2.0f, -2.0f);
    __syncthreads();   // z staging region now free -> becomes B buffers

    // ---- prefetch chunk 0; load wnorm table ----
    issue_chunk(sb, 0, 0, tid); CP_COMMIT();
    {
        float* sWN = reinterpret_cast<float*>(smp + SM_WN);
#pragma unroll
        for (int i = 0; i < KK / THREADS; i++)
            sWN[tid + i * THREADS] = g_wnorm[tid + i * THREADS];
    }

    float dmin[4] = {3.4e38f, 3.4e38f, 3.4e38f, 3.4e38f};
    int imin[4] = {0, 0, 0, 0};

    // ---- pipeline: ONE barrier per chunk, 2 buffers, prefetch distance 1 ----
    // iter c: wait(c resident) -> barrier(retires reads of c-1, and wnorm/A-frag
    // visibility at c=0) -> issue c+1 into buf (c+1)&1 (last used by c-1, now free)
    // -> process c. cp(c+1) overlaps the full MMA+epilogue of chunk c.
    for (int c = 0; c < NCHUNKS; c++) {
        CP_WAIT(0);
        __syncthreads();
        if (c + 1 < NCHUNKS) { issue_chunk(sb, c + 1, (c + 1) & 1, tid); CP_COMMIT(); }
        process_chunk(smp, c, g, t, ah, al, zpkA, zpkB, NEG2, dmin, imin);
    }

    // ---- cross-lane reduce over the t-quad (smaller index wins ties) ----
#pragma unroll
    for (int s = 0; s < 4; s++) {
#pragma unroll
        for (int o = 1; o < 4; o <<= 1) {
            float od = __shfl_xor_sync(0xffffffff, dmin[s], o);
            int   oi = __shfl_xor_sync(0xffffffff, imin[s], o);
            if (od < dmin[s] || (od == dmin[s] && oi < imin[s])) { dmin[s] = od; imin[s] = oi; }
        }
    }
    const int my = (t == 0) ? imin[0] : (t == 1) ? imin[1] : (t == 2) ? imin[2] : imin[3];

    // ---- outputs: codes, z_q_st = z + (w - z), loss partial ----
    const int rown = w * 32 + g + 8 * t;
    const int grow = blockIdx.x * THREADS + rown;
    out_codes[grow] = (float)my;

    const int b = grow >> 13;
    const int tp = grow & (TT - 1);
    const float* zp = z + (size_t)b * DD * TT + tp;
    float* oz = out_zq + (size_t)b * DD * TT + tp;
    const float4* wrow = reinterpret_cast<const float4*>(W + (size_t)my * DD);
    float lsum = 0.0f;
#pragma unroll
    for (int j = 0; j < 16; j++) {
        float4 wv = wrow[j];
        float wa[4] = {wv.x, wv.y, wv.z, wv.w};
#pragma unroll
        for (int q = 0; q < 4; q++) {
            float zv = zp[(size_t)(4 * j + q) * TT];
            float e = __fsub_rn(wa[q], zv);
            oz[(size_t)(4 * j + q) * TT] = __fadd_rn(zv, e);   // straight-through estimator
            lsum = __fadd_rn(lsum, __fmul_rn(e, e));
        }
    }

    float* sRed = reinterpret_cast<float*>(smp + SM_RED);
    sRed[tid] = lsum;
    __syncthreads();
#pragma unroll
    for (int s = THREADS / 2; s > 0; s >>= 1) {
        if (tid < s) sRed[tid] += sRed[tid + s];
        __syncthreads();
    }

    // ---- fused finalize: last block reduces all partials (deterministic order) ----
    __shared__ unsigned int sIsLast;
    if (tid == 0) {
        g_partial[blockIdx.x] = sRed[0];
        __threadfence();
        unsigned int tk = atomicAdd(&g_ticket, 1u);
        sIsLast = (tk == NBLOCKS - 1) ? 1u : 0u;
    }
    __syncthreads();
    if (sIsLast) {
        float v = __fadd_rn(__fadd_rn(g_partial[tid], g_partial[tid + 128]),
                            __fadd_rn(g_partial[tid + 256], g_partial[tid + 384]));
        sRed[tid] = v;
        __syncthreads();
#pragma unroll
        for (int s = THREADS / 2; s > 0; s >>= 1) {
            if (tid < s) sRed[tid] += sRed[tid + s];
            __syncthreads();
        }
        if (tid == 0) {
            out_loss[0] = 1.25f * (sRed[0] / (float)NZ);
            g_ticket = 0;    // reset for next graph replay
        }
    }
}

extern "C" void kernel_launch(void* const* d_in, const int* in_sizes, int n_in,
                              void* d_out, int out_size) {
    const float* z = (const float*)d_in[0];      // [8, 64, 8192]
    const float* W = (const float*)d_in[1];      // [1024, 64]
    float* out = (float*)d_out;
    float* out_zq    = out;
    float* out_loss  = out + NZ;
    float* out_codes = out + NZ + 1;

    vq_prep_kernel<<<32, 32>>>(W);
    vq_main_kernel<<<NBLOCKS, THREADS>>>(z, W, out_zq, out_codes, out_loss);
}